// round 4
// baseline (speedup 1.0000x reference)
#include <cuda_runtime.h>

#define NPTS   300000
#define NPAIRS 100000
#define KOFF   27
#define CIN    32
#define COUT   64
#define NGRP   8

// ---- scratch (no allocations allowed) ----
__device__ float g_sum[NGRP];
__device__ float g_sq[NGRP];
__device__ float g_mean[NGRP];
__device__ float g_inv[NGRP];
__device__ int   g_is64;

// Detect whether index arrays are int64 or int32 (jax x64 flag ambiguity).
// If int64, every high 32-bit word is 0 (all indices < 300000).
__global__ void detect_kernel(const unsigned int* __restrict__ idx32) {
    __shared__ int s_any;
    if (threadIdx.x == 0) s_any = 0;
    __syncthreads();
    unsigned int v = 0;
    for (int i = threadIdx.x; i < 2048; i += blockDim.x)
        v |= idx32[2 * i + 1];
    if (v) atomicOr(&s_any, 1);
    __syncthreads();
    if (threadIdx.x == 0) g_is64 = (s_any == 0) ? 1 : 0;
}

__global__ void zero_kernel(float4* __restrict__ out, int n4) {
    int i = blockIdx.x * blockDim.x + threadIdx.x;
    if (i < n4) out[i] = make_float4(0.f, 0.f, 0.f, 0.f);
    if (blockIdx.x == 0 && threadIdx.x < NGRP) {
        g_sum[threadIdx.x] = 0.f;
        g_sq[threadIdx.x]  = 0.f;
    }
}

__device__ __forceinline__ long long load_idx(const void* p, long long pos, int is64) {
    if (is64) return ((const long long*)p)[pos];
    return (long long)((const int*)p)[pos];
}

// Sparse conv: one warp per pair. Lane l owns output channels l and l+32.
// W_k staged smem -> 64 registers/lane; feature row read as 8 broadcast float4 loads.
__global__ __launch_bounds__(256, 2)
void conv_kernel(const float* __restrict__ feats,
                 const float* __restrict__ weight,
                 const void*  __restrict__ in_idx,
                 const void*  __restrict__ out_idx,
                 float*       __restrict__ out) {
    const int k    = blockIdx.y;
    const int lane = threadIdx.x & 31;
    const int warp = threadIdx.x >> 5;

    __shared__ float ws[CIN * COUT];
    const float* wk = weight + (long long)k * CIN * COUT;
    for (int i = threadIdx.x; i < CIN * COUT; i += blockDim.x) ws[i] = wk[i];
    __syncthreads();

    float w0[CIN], w1[CIN];
#pragma unroll
    for (int i = 0; i < CIN; i++) {
        w0[i] = ws[i * COUT + lane];
        w1[i] = ws[i * COUT + lane + 32];
    }

    const int is64 = g_is64;
    const long long base = (long long)k * NPAIRS;
    const int p0 = (blockIdx.x * 8 + warp) * 32;
    if (p0 >= NPAIRS) return;

    const int p = p0 + lane;
    long long ir = 0, orow = 0;
    if (p < NPAIRS) {
        ir   = load_idx(in_idx,  base + p, is64);
        orow = load_idx(out_idx, base + p, is64);
    }
    const int nv = min(32, NPAIRS - p0);

    for (int j = 0; j < nv; j++) {
        long long irow = __shfl_sync(0xffffffffu, ir,   j);
        long long ro   = __shfl_sync(0xffffffffu, orow, j);
        const float4* f4 = (const float4*)(feats + irow * CIN);
        float a0 = 0.f, a1 = 0.f;
#pragma unroll
        for (int c = 0; c < 8; c++) {
            float4 fv = __ldg(f4 + c);      // broadcast: same addr all lanes
            a0 = fmaf(fv.x, w0[4*c+0], a0);  a1 = fmaf(fv.x, w1[4*c+0], a1);
            a0 = fmaf(fv.y, w0[4*c+1], a0);  a1 = fmaf(fv.y, w1[4*c+1], a1);
            a0 = fmaf(fv.z, w0[4*c+2], a0);  a1 = fmaf(fv.z, w1[4*c+2], a1);
            a0 = fmaf(fv.w, w0[4*c+3], a0);  a1 = fmaf(fv.w, w1[4*c+3], a1);
        }
        float* op = out + ro * COUT;
        atomicAdd(op + lane,      a0);
        atomicAdd(op + lane + 32, a1);
    }
}

// GroupNorm stats: block (64,4). threadIdx.x = channel, threadIdx.y = row phase.
__global__ void stats_kernel(const float* __restrict__ out) {
    __shared__ float s_sum[NGRP], s_sq[NGRP];
    const int c = threadIdx.x;  // 0..63
    if (threadIdx.y == 0 && c < NGRP) { s_sum[c] = 0.f; s_sq[c] = 0.f; }
    __syncthreads();

    float sum = 0.f, sq = 0.f;
    for (int row = blockIdx.x * 4 + threadIdx.y; row < NPTS; row += gridDim.x * 4) {
        float v = out[(long long)row * COUT + c];
        sum += v;
        sq = fmaf(v, v, sq);
    }
    // reduce within 8-lane channel-group segments (lane == c mod 32, 8-aligned)
#pragma unroll
    for (int off = 4; off; off >>= 1) {
        sum += __shfl_down_sync(0xffffffffu, sum, off, 8);
        sq  += __shfl_down_sync(0xffffffffu, sq,  off, 8);
    }
    if ((c & 7) == 0) {
        atomicAdd(&s_sum[c >> 3], sum);
        atomicAdd(&s_sq[c >> 3],  sq);
    }
    __syncthreads();
    if (threadIdx.y == 0 && c < NGRP) {
        atomicAdd(&g_sum[c], s_sum[c]);
        atomicAdd(&g_sq[c],  s_sq[c]);
    }
}

__global__ void finalize_kernel() {
    int g = threadIdx.x;
    if (g < NGRP) {
        const float cnt = (float)NPTS * (COUT / NGRP);
        float m   = g_sum[g] / cnt;
        float var = g_sq[g] / cnt - m * m;
        g_mean[g] = m;
        g_inv[g]  = rsqrtf(var + 1e-5f);
    }
}

// Fused affine + LeakyReLU: y = x*(inv*gamma) + (beta - m*inv*gamma)
__global__ void norm_kernel(float* __restrict__ out,
                            const float* __restrict__ gamma,
                            const float* __restrict__ beta) {
    const int c = threadIdx.x;
    const int g = c >> 3;
    const float m   = g_mean[g];
    const float inv = g_inv[g];
    const float ga  = gamma[c] * inv;
    const float be  = beta[c] - m * ga;
    for (int row = blockIdx.x * 4 + threadIdx.y; row < NPTS; row += gridDim.x * 4) {
        long long idx = (long long)row * COUT + c;
        float v = fmaf(out[idx], ga, be);
        out[idx] = (v >= 0.f) ? v : 0.01f * v;
    }
}

extern "C" void kernel_launch(void* const* d_in, const int* in_sizes, int n_in,
                              void* d_out, int out_size) {
    const float* feats   = (const float*)d_in[0];
    const float* weight  = (const float*)d_in[1];
    const float* gamma   = (const float*)d_in[2];
    const float* beta    = (const float*)d_in[3];
    const void*  in_idx  = d_in[4];
    const void*  out_idx = d_in[5];
    float* out = (float*)d_out;

    detect_kernel<<<1, 256>>>((const unsigned int*)in_idx);

    const int n4 = NPTS * COUT / 4;
    zero_kernel<<<(n4 + 255) / 256, 256>>>((float4*)out, n4);

    dim3 cgrid((NPAIRS + 255) / 256, KOFF);   // 391 x 27 blocks, 8 warps each
    conv_kernel<<<cgrid, 256>>>(feats, weight, in_idx, out_idx, out);

    dim3 blk(64, 4);
    stats_kernel<<<1184, blk>>>(out);
    finalize_kernel<<<1, 32>>>();
    norm_kernel<<<2048, blk>>>(out, gamma, beta);
}

// round 5
// speedup vs baseline: 1.0801x; 1.0801x over previous
#include <cuda_runtime.h>

#define NPTS   300000
#define NPAIRS 100000
#define KOFF   27
#define CIN    32
#define COUT   64
#define NGRP   8

// ---- scratch (no allocations allowed) ----
__device__ float g_sum[NGRP];
__device__ float g_sq[NGRP];
__device__ float g_mean[NGRP];
__device__ float g_inv[NGRP];
__device__ int   g_is64;

// ---- packed fp32x2 helpers (sm_100+) ----
__device__ __forceinline__ unsigned long long pack2(float lo, float hi) {
    unsigned long long r;
    asm("mov.b64 %0, {%1, %2};" : "=l"(r) : "f"(lo), "f"(hi));
    return r;
}
__device__ __forceinline__ float hadd2(unsigned long long v) {
    float lo, hi;
    asm("mov.b64 {%0, %1}, %2;" : "=f"(lo), "=f"(hi) : "l"(v));
    return lo + hi;
}
#define FMA2(acc, b, w) \
    asm("fma.rn.f32x2 %0, %1, %2, %0;" : "+l"(acc) : "l"(b), "l"(w))

__device__ __forceinline__ void red_add_v2(float* addr, float x, float y) {
    asm volatile("red.global.add.v2.f32 [%0], {%1, %2};"
                 :: "l"(addr), "f"(x), "f"(y) : "memory");
}

// Detect whether index arrays are int64 or int32 (jax x64 flag ambiguity).
// If int64, every high 32-bit word of the first 4K entries is 0.
__global__ void detect_kernel(const unsigned int* __restrict__ idx32) {
    __shared__ int s_any;
    if (threadIdx.x == 0) s_any = 0;
    __syncthreads();
    unsigned int v = 0;
    for (int i = threadIdx.x; i < 2048; i += blockDim.x)
        v |= idx32[2 * i + 1];
    if (v) atomicOr(&s_any, 1);
    __syncthreads();
    if (threadIdx.x == 0) g_is64 = (s_any == 0) ? 1 : 0;
}

__global__ void zero_kernel(float4* __restrict__ out, int n4) {
    int i = blockIdx.x * blockDim.x + threadIdx.x;
    if (i < n4) out[i] = make_float4(0.f, 0.f, 0.f, 0.f);
    if (blockIdx.x == 0 && threadIdx.x < NGRP) {
        g_sum[threadIdx.x] = 0.f;
        g_sq[threadIdx.x]  = 0.f;
    }
}

__device__ __forceinline__ int load_idx(const void* p, long long pos, int is64) {
    if (is64) return (int)((const long long*)p)[pos];
    return ((const int*)p)[pos];
}

// Sparse conv: one warp per batch of 32 pairs. Lane l owns output channels
// (2l, 2l+1). Accumulators are f32x2 pairs: .lo sums even input channels,
// .hi sums odd input channels; one horizontal add at the end. Feature row
// read as 8 broadcast 128-bit loads whose register pairs feed fma.rn.f32x2
// directly (no repacking in the loop). Scatter via red.global.add.v2.f32.
__global__ __launch_bounds__(256, 2)
void conv_kernel(const float* __restrict__ feats,
                 const float* __restrict__ weight,
                 const void*  __restrict__ in_idx,
                 const void*  __restrict__ out_idx,
                 float*       __restrict__ out) {
    const int k    = blockIdx.y;
    const int lane = threadIdx.x & 31;
    const int warp = threadIdx.x >> 5;

    __shared__ float ws[CIN * COUT];
    const float* wk = weight + (long long)k * CIN * COUT;
    for (int i = threadIdx.x; i < CIN * COUT; i += blockDim.x) ws[i] = wk[i];
    __syncthreads();

    // wp0[c2] = (W[2c2][2l], W[2c2+1][2l]) ; wp1 same for channel 2l+1
    unsigned long long wp0[16], wp1[16];
#pragma unroll
    for (int c2 = 0; c2 < 16; c2++) {
        wp0[c2] = pack2(ws[(2*c2) * COUT + 2*lane],     ws[(2*c2+1) * COUT + 2*lane]);
        wp1[c2] = pack2(ws[(2*c2) * COUT + 2*lane + 1], ws[(2*c2+1) * COUT + 2*lane + 1]);
    }

    const int is64 = g_is64;
    const long long base = (long long)k * NPAIRS;
    const int p0 = (blockIdx.x * 8 + warp) * 32;
    if (p0 >= NPAIRS) return;

    const int p = p0 + lane;
    int ir = 0, orow = 0;
    if (p < NPAIRS) {
        ir   = load_idx(in_idx,  base + p, is64);
        orow = load_idx(out_idx, base + p, is64);
    }
    const int nv = min(32, NPAIRS - p0);

    for (int j = 0; j < nv; j++) {
        const int irow = __shfl_sync(0xffffffffu, ir,   j);
        const int ro   = __shfl_sync(0xffffffffu, orow, j);
        const ulonglong2* f2 = (const ulonglong2*)(feats + (long long)irow * CIN);
        unsigned long long a0 = 0ull, a1 = 0ull;  // bits of (0.f, 0.f)
#pragma unroll
        for (int q = 0; q < 8; q++) {
            ulonglong2 fv = __ldg(f2 + q);          // broadcast, 4 floats = 2 pairs
            FMA2(a0, fv.x, wp0[2*q]);   FMA2(a1, fv.x, wp1[2*q]);
            FMA2(a0, fv.y, wp0[2*q+1]); FMA2(a1, fv.y, wp1[2*q+1]);
        }
        red_add_v2(out + (long long)ro * COUT + 2*lane, hadd2(a0), hadd2(a1));
    }
}

// GroupNorm stats: float4 loads; 4 channels per thread all lie in one group
// (group = c4>>1). Two butterfly shuffles fold warp partials per group.
__global__ void stats_kernel(const float4* __restrict__ out) {
    const int c4   = threadIdx.x & 15;   // float4 column 0..15
    const int ty   = threadIdx.x >> 4;   // row phase 0..15
    const int lane = threadIdx.x & 31;
    __shared__ float s_sum[NGRP], s_sq[NGRP];
    if (threadIdx.x < NGRP) { s_sum[threadIdx.x] = 0.f; s_sq[threadIdx.x] = 0.f; }
    __syncthreads();

    float sum = 0.f, sq = 0.f;
#pragma unroll 4
    for (int row = blockIdx.x * 16 + ty; row < NPTS; row += gridDim.x * 16) {
        float4 v = __ldg(out + row * 16 + c4);
        sum += (v.x + v.y) + (v.z + v.w);
        sq   = fmaf(v.x, v.x, fmaf(v.y, v.y, fmaf(v.z, v.z, fmaf(v.w, v.w, sq))));
    }
    // lanes {2g, 2g+1, 2g+16, 2g+17} share group g
    sum += __shfl_xor_sync(0xffffffffu, sum, 16);
    sq  += __shfl_xor_sync(0xffffffffu, sq,  16);
    sum += __shfl_xor_sync(0xffffffffu, sum, 1);
    sq  += __shfl_xor_sync(0xffffffffu, sq,  1);
    if (lane < 16 && !(lane & 1)) {
        atomicAdd(&s_sum[lane >> 1], sum);
        atomicAdd(&s_sq[lane >> 1],  sq);
    }
    __syncthreads();
    if (threadIdx.x < NGRP) {
        atomicAdd(&g_sum[threadIdx.x], s_sum[threadIdx.x]);
        atomicAdd(&g_sq[threadIdx.x],  s_sq[threadIdx.x]);
    }
}

__global__ void finalize_kernel() {
    int g = threadIdx.x;
    if (g < NGRP) {
        const float cnt = (float)NPTS * (COUT / NGRP);
        float m   = g_sum[g] / cnt;
        float var = g_sq[g] / cnt - m * m;
        g_mean[g] = m;
        g_inv[g]  = rsqrtf(var + 1e-5f);
    }
}

// Fused affine + LeakyReLU, float4 in/out: y = x*(inv*gamma) + (beta - m*inv*gamma)
__global__ void norm_kernel(float4* __restrict__ out,
                            const float4* __restrict__ gamma4,
                            const float4* __restrict__ beta4) {
    const int c4 = threadIdx.x & 15;
    const int ty = threadIdx.x >> 4;
    const int g  = c4 >> 1;
    const float m   = g_mean[g];
    const float inv = g_inv[g];
    float4 ga = __ldg(gamma4 + c4);
    float4 be = __ldg(beta4  + c4);
    ga.x *= inv; ga.y *= inv; ga.z *= inv; ga.w *= inv;
    be.x -= m * ga.x; be.y -= m * ga.y; be.z -= m * ga.z; be.w -= m * ga.w;
#pragma unroll 4
    for (int row = blockIdx.x * 16 + ty; row < NPTS; row += gridDim.x * 16) {
        float4 v = out[row * 16 + c4];
        v.x = fmaf(v.x, ga.x, be.x); v.x = (v.x >= 0.f) ? v.x : 0.01f * v.x;
        v.y = fmaf(v.y, ga.y, be.y); v.y = (v.y >= 0.f) ? v.y : 0.01f * v.y;
        v.z = fmaf(v.z, ga.z, be.z); v.z = (v.z >= 0.f) ? v.z : 0.01f * v.z;
        v.w = fmaf(v.w, ga.w, be.w); v.w = (v.w >= 0.f) ? v.w : 0.01f * v.w;
        out[row * 16 + c4] = v;
    }
}

extern "C" void kernel_launch(void* const* d_in, const int* in_sizes, int n_in,
                              void* d_out, int out_size) {
    const float* feats   = (const float*)d_in[0];
    const float* weight  = (const float*)d_in[1];
    const float* gamma   = (const float*)d_in[2];
    const float* beta    = (const float*)d_in[3];
    const void*  in_idx  = d_in[4];
    const void*  out_idx = d_in[5];
    float* out = (float*)d_out;

    detect_kernel<<<1, 256>>>((const unsigned int*)in_idx);

    const int n4 = NPTS * COUT / 4;
    zero_kernel<<<(n4 + 255) / 256, 256>>>((float4*)out, n4);

    dim3 cgrid((NPAIRS + 255) / 256, KOFF);   // 391 x 27 blocks, 8 warps each
    conv_kernel<<<cgrid, 256>>>(feats, weight, in_idx, out_idx, out);

    stats_kernel<<<1184, 256>>>((const float4*)out);
    finalize_kernel<<<1, 32>>>();
    norm_kernel<<<2048, 256>>>((float4*)out, (const float4*)gamma, (const float4*)beta);
}